// round 12
// baseline (speedup 1.0000x reference)
#include <cuda_runtime.h>
#include <cuda_fp16.h>
#include <cstdint>

#define N_B 16
#define IC  256
#define OC  256
#define HH  64
#define WW  64
#define SD  512
#define EPSV 1e-8f

// Karatsuba fold scale: corrections = one MMA of (AL + EPS*AH)(BH + BL/EPS)
#define EPS_F   0.015625f      // 2^-6
#define EPS_INV 64.0f          // 2^6
#define ONE_M_EPS 0.984375f    // 1 - 2^-6 (exact in fp32)

// ---------------- device scratch ----------------
__device__ float g_m[N_B * IC];
__device__ float g_demod[N_B * OC];
__device__ float g_wsq[IC * OC];
// V: [pt(36)][mblock(32)][kc(4)][plane(2: hi, folded-corr)][128 rows x 64 ic swizzled] fp16
__device__ __align__(16) __half g_V[36 * 32 * 4 * 2 * 8192];
// U: [pt(36)][nh(2)][kc(4)][plane(2: hi, folded-corr)][128 oc x 64 ic swizzled] fp16
__device__ __align__(16) __half g_U[36 * 2 * 4 * 2 * 8192];
// M: [pt(36)][oc(256)][flat_tile(4096)] fp32
__device__ float g_M[36 * 256 * 4096];

// ---------------- PTX helpers ----------------
__device__ __forceinline__ uint32_t smem_u32(const void* p) {
    uint32_t a;
    asm("{ .reg .u64 t; cvta.to.shared.u64 t, %1; cvt.u32.u64 %0, t; }" : "=r"(a) : "l"(p));
    return a;
}
#define LDSM_X4(r0, r1, r2, r3, addr) \
    asm volatile("ldmatrix.sync.aligned.m8n8.x4.shared.b16 {%0,%1,%2,%3}, [%4];" \
        : "=r"(r0), "=r"(r1), "=r"(r2), "=r"(r3) : "r"(addr))
#define MMA16816(c, a, b0, b1) \
    asm volatile("mma.sync.aligned.m16n8k16.row.col.f32.f16.f16.f32 " \
        "{%0,%1,%2,%3}, {%4,%5,%6,%7}, {%8,%9}, {%0,%1,%2,%3};" \
        : "+f"((c)[0]), "+f"((c)[1]), "+f"((c)[2]), "+f"((c)[3]) \
        : "r"((a)[0]), "r"((a)[1]), "r"((a)[2]), "r"((a)[3]), "r"(b0), "r"(b1))
#define CP_ASYNC16(dst, src) \
    asm volatile("cp.async.cg.shared.global [%0], [%1], 16;" :: "r"(dst), "l"(src))
#define CP_COMMIT() asm volatile("cp.async.commit_group;")

// ---------------- prep kernels ----------------
__global__ void mod_kernel(const float* __restrict__ style,
                           const float* __restrict__ mod_w,
                           const float* __restrict__ mod_b) {
    int n = blockIdx.x, i = threadIdx.x;
    __shared__ float ss[SD];
    for (int k = threadIdx.x; k < SD; k += blockDim.x) ss[k] = style[n * SD + k];
    __syncthreads();
    float acc = 0.f;
    const float* wr = mod_w + i * SD;
#pragma unroll 8
    for (int k = 0; k < SD; k++) acc += ss[k] * wr[k];
    g_m[n * IC + i] = acc + mod_b[i] + 1.0f;
}

__global__ void demod_kernel() {
    int n = blockIdx.x, o = threadIdx.x;
    __shared__ float ms[IC];
    ms[threadIdx.x] = g_m[n * IC + threadIdx.x];
    __syncthreads();
    float acc = EPSV;
#pragma unroll 8
    for (int i = 0; i < IC; i++) acc += ms[i] * ms[i] * g_wsq[i * OC + o];
    g_demod[n * OC + o] = rsqrtf(acc);
}

// ---------------- weight transform: U = G g G^T, Karatsuba-fold split + swizzle
// also computes wsq (fused) ----------------
__global__ void wT_kernel(const float* __restrict__ weight) {
    int idx = blockIdx.x * 256 + threadIdx.x;   // 0..65535
    int oc = idx >> 8, ic = idx & 255;
    float g[3][3];
    float sq = 0.f;
#pragma unroll
    for (int r = 0; r < 3; r++)
#pragma unroll
        for (int c = 0; c < 3; c++) {
            float w = weight[(oc * IC + ic) * 9 + r * 3 + c];
            g[r][c] = w;
            sq += w * w;
        }
    g_wsq[ic * OC + oc] = sq;

    float t[6][3];
#pragma unroll
    for (int c = 0; c < 3; c++) {
        float g0 = g[0][c], g1 = g[1][c], g2 = g[2][c];
        t[0][c] = 0.25f * g0;
        t[1][c] = (-g0 - g1 - g2) * (1.f / 6.f);
        t[2][c] = (-g0 + g1 - g2) * (1.f / 6.f);
        t[3][c] = g0 * (1.f / 24.f) + g1 * (1.f / 12.f) + g2 * (1.f / 6.f);
        t[4][c] = g0 * (1.f / 24.f) - g1 * (1.f / 12.f) + g2 * (1.f / 6.f);
        t[5][c] = g2;
    }
    const int nh = oc >> 7, oc128 = oc & 127;
    const int kc = ic >> 6, icc = ic & 63, kg = icc >> 3, kl = icc & 7;
    const int off16 = oc128 * 64 + ((kg ^ (oc128 & 7)) << 3) + kl;
#pragma unroll
    for (int r = 0; r < 6; r++) {
        float t0 = t[r][0], t1 = t[r][1], t2 = t[r][2];
        float u[6];
        u[0] = 0.25f * t0;
        u[1] = (-t0 - t1 - t2) * (1.f / 6.f);
        u[2] = (-t0 + t1 - t2) * (1.f / 6.f);
        u[3] = t0 * (1.f / 24.f) + t1 * (1.f / 12.f) + t2 * (1.f / 6.f);
        u[4] = t0 * (1.f / 24.f) - t1 * (1.f / 12.f) + t2 * (1.f / 6.f);
        u[5] = t2;
#pragma unroll
        for (int c = 0; c < 6; c++) {
            int pt = r * 6 + c;
            __half h = __float2half_rn(u[c]);
            float hf = __half2float(h);
            __half bcv = __float2half_rn(hf + EPS_INV * (u[c] - hf));   // Bc = BH + BL/eps
            size_t base = ((size_t)(((pt * 2 + nh) * 4 + kc) * 2)) * 8192;
            g_U[base + off16] = h;
            g_U[base + 8192 + off16] = bcv;
        }
    }
}

// ---------------- input transform: V = B^T (x*m) B, Karatsuba-fold split + swizzle
// All 36 points staged into smem, ONE barrier, one batched flush.
#define SM_INT (36 * 16 * 24 * 2)       // bytes per plane: 27648
__global__ __launch_bounds__(256) void inT_kernel(const float* __restrict__ x) {
    extern __shared__ __align__(16) unsigned char smem[];
    __half* sH = (__half*)smem;                    // [36][16][24]
    __half* sL = (__half*)(smem + SM_INT);

    const int icg = blockIdx.x;            // 16-ic group (0..15)
    const int th  = blockIdx.y;            // tile row (0..15)
    const int n   = blockIdx.z;
    const int tid = threadIdx.x;
    const int tw  = tid & 15, icl = tid >> 4;
    const int ic  = icg * 16 + icl;

    const float mm = g_m[n * IC + ic];
    const float* xp = x + ((size_t)(n * IC + ic)) * 4096;

    float d[6][6];
#pragma unroll
    for (int r = 0; r < 6; r++) {
        int gh = th * 4 + r - 1;
#pragma unroll
        for (int c = 0; c < 6; c++) {
            int gw = tw * 4 + c - 1;
            d[r][c] = ((unsigned)gh < HH && (unsigned)gw < WW) ? xp[gh * 64 + gw] * mm : 0.f;
        }
    }
    float t[6][6];
#pragma unroll
    for (int c = 0; c < 6; c++) {
        float d0 = d[0][c], d1 = d[1][c], d2 = d[2][c], d3 = d[3][c], d4 = d[4][c], d5 = d[5][c];
        t[0][c] = 4.f * d0 - 5.f * d2 + d4;
        t[1][c] = -4.f * d1 - 4.f * d2 + d3 + d4;
        t[2][c] = 4.f * d1 - 4.f * d2 - d3 + d4;
        t[3][c] = -2.f * d1 - d2 + 2.f * d3 + d4;
        t[4][c] = 2.f * d1 - d2 - 2.f * d3 + d4;
        t[5][c] = 4.f * d1 - 5.f * d3 + d5;
    }

#pragma unroll
    for (int r = 0; r < 6; r++) {
        float t0 = t[r][0], t1 = t[r][1], t2 = t[r][2], t3 = t[r][3], t4 = t[r][4], t5 = t[r][5];
        float v[6];
        v[0] = 4.f * t0 - 5.f * t2 + t4;
        v[1] = -4.f * t1 - 4.f * t2 + t3 + t4;
        v[2] = 4.f * t1 - 4.f * t2 - t3 + t4;
        v[3] = -2.f * t1 - t2 + 2.f * t3 + t4;
        v[4] = 2.f * t1 - t2 - 2.f * t3 + t4;
        v[5] = 4.f * t1 - 5.f * t3 + t5;
#pragma unroll
        for (int c = 0; c < 6; c++) {
            __half h = __float2half_rn(v[c]);
            float hf = __half2float(h);
            __half acv = __float2half_rn((v[c] - hf) + EPS_F * hf);   // Ac = AL + eps*AH
            int off = ((r * 6 + c) * 16 + tw) * 24 + icl;
            sH[off] = h;
            sL[off] = acv;
        }
    }
    __syncthreads();

    const int mb = n * 2 + (th >> 3);
    const int kc = icg >> 2;
    const int rowbase = (th & 7) * 16;

    // flush: 36 pts x 2 planes x 16 rows x 2 granules = 2304 uint4 -> 9/thread
#pragma unroll
    for (int k = 0; k < 9; k++) {
        int it = tid + k * 256;
        int pt = it / 64;
        int rest = it & 63;
        int plane = rest >> 5;
        int e = rest & 31;
        int rw = e >> 1, gsel = e & 1;
        int kg = (icg & 3) * 2 + gsel;
        const __half* srcp = plane ? sL : sH;
        const uint4* src = (const uint4*)(srcp + (pt * 16 + rw) * 24 + gsel * 8);
        size_t base = ((size_t)(((pt * 32 + mb) * 4 + kc) * 2 + plane)) * 8192;
        *(uint4*)(g_V + base + (rowbase + rw) * 64 + ((kg ^ (rw & 7)) << 3)) = *src;
    }
}

// ---------------- batched GEMM: M[pt] = V[pt] * U[pt]^T ----------------
// CTA = M-tile 64 x FULL N=256 (V read once per tile, not twice).
// hi*hi fp32-acc + one folded correction MMA per n8 per k16.
#define STAGE_B 81920      // per stage: Ahi 8K | Acorr 8K | Bhi(256oc) 32K | Bcorr 32K
#define SMEM_G  (2 * STAGE_B)
__global__ __launch_bounds__(256, 1)
void wino_gemm() {
    extern __shared__ __align__(128) unsigned char smem[];
    const uint32_t sb = smem_u32(smem);
    const int tid = threadIdx.x;
    const int wid = tid >> 5, lane = tid & 31;
    const int mb = blockIdx.x;             // 0..63 (64-row block)
    const int pt = blockIdx.y;             // 0..35
    const int mb2 = mb >> 1, hb = mb & 1;

    const int warp_m = wid & 1, warp_n = wid >> 1;   // warp_n: 4 warps x 64 oc
    const int pxr0 = warp_m * 32 + (lane & 15);
    const int aksel = lane >> 4;
    const uint32_t bboff = (uint32_t)(warp_n * 64 + ((lane >> 4) << 3) + (lane & 7)) * 128;
    const int bksel = (lane >> 3) & 1;
    const int bswz = lane & 7;

    float acc[2][8][4];
    float accC[2][8][4];
#pragma unroll
    for (int a = 0; a < 2; a++)
#pragma unroll
        for (int b = 0; b < 8; b++)
#pragma unroll
            for (int q = 0; q < 4; q++) { acc[a][b][q] = 0.f; accC[a][b][q] = 0.f; }

    // prologue: chunk 0 -> stage 0
    {
#pragma unroll
        for (int p = 0; p < 2; p++) {
            const char* As = (const char*)(g_V + ((size_t)(((pt * 32 + mb2) * 4 + 0) * 2 + p)) * 8192 + (size_t)hb * 4096);
#pragma unroll
            for (int i = 0; i < 2; i++)
                CP_ASYNC16(sb + p * 8192 + (tid + i * 256) * 16, As + (tid + i * 256) * 16);
#pragma unroll
            for (int nh = 0; nh < 2; nh++) {
                const char* Bs = (const char*)(g_U + ((size_t)(((pt * 2 + nh) * 4 + 0) * 2 + p)) * 8192);
#pragma unroll
                for (int i = 0; i < 4; i++)
                    CP_ASYNC16(sb + 16384 + p * 32768 + nh * 16384 + (tid + i * 256) * 16,
                               Bs + (tid + i * 256) * 16);
            }
        }
        CP_COMMIT();
    }

#pragma unroll 1
    for (int kc = 0; kc < 4; kc++) {
        const int s = kc & 1;
        __syncthreads();
        if (kc + 1 < 4) {
            uint32_t dA = sb + (s ^ 1) * STAGE_B;
#pragma unroll
            for (int p = 0; p < 2; p++) {
                const char* As = (const char*)(g_V + ((size_t)(((pt * 32 + mb2) * 4 + kc + 1) * 2 + p)) * 8192 + (size_t)hb * 4096);
#pragma unroll
                for (int i = 0; i < 2; i++)
                    CP_ASYNC16(dA + p * 8192 + (tid + i * 256) * 16, As + (tid + i * 256) * 16);
#pragma unroll
                for (int nh = 0; nh < 2; nh++) {
                    const char* Bs = (const char*)(g_U + ((size_t)(((pt * 2 + nh) * 4 + kc + 1) * 2 + p)) * 8192);
#pragma unroll
                    for (int i = 0; i < 4; i++)
                        CP_ASYNC16(dA + 16384 + p * 32768 + nh * 16384 + (tid + i * 256) * 16,
                                   Bs + (tid + i * 256) * 16);
                }
            }
            CP_COMMIT();
            asm volatile("cp.async.wait_group 1;");
        } else {
            asm volatile("cp.async.wait_group 0;");
        }
        __syncthreads();

        const uint32_t Abase = sb + s * STAGE_B;
        // B layout in stage: [plane hi @16384 | plane corr @49152], each plane: 256 oc rows x 128B
        const uint32_t Bbase = Abase + 16384 + bboff;
#pragma unroll
        for (int st = 0; st < 4; st++) {
            uint32_t AH[2][4], AC[2][4];
#pragma unroll
            for (int mt = 0; mt < 2; mt++) {
                int row = pxr0 + mt * 16;
                int kg = 2 * st + aksel;
                uint32_t a = Abase + (uint32_t)row * 128 + ((uint32_t)(kg ^ (row & 7)) << 4);
                LDSM_X4(AH[mt][0], AH[mt][1], AH[mt][2], AH[mt][3], a);
                LDSM_X4(AC[mt][0], AC[mt][1], AC[mt][2], AC[mt][3], a + 8192);
            }
            int kgb = 2 * st + bksel;
            uint32_t boff = (uint32_t)((kgb ^ bswz) << 4);
#pragma unroll
            for (int og = 0; og < 4; og++) {
                uint32_t BH[4], BC[4];
                uint32_t ba = Bbase + og * 2048 + boff;
                LDSM_X4(BH[0], BH[1], BH[2], BH[3], ba);
                LDSM_X4(BC[0], BC[1], BC[2], BC[3], ba + 32768);
#pragma unroll
                for (int mt = 0; mt < 2; mt++) {
                    MMA16816(acc[mt][og * 2],      AH[mt], BH[0], BH[1]);
                    MMA16816(acc[mt][og * 2 + 1],  AH[mt], BH[2], BH[3]);
                    MMA16816(accC[mt][og * 2],     AC[mt], BC[0], BC[1]);
                    MMA16816(accC[mt][og * 2 + 1], AC[mt], BC[2], BC[3]);
                }
            }
        }
    }

    // epilogue: final = acc_hi*(1-eps) + acc_corr ; store M
    float* Mp = g_M + (size_t)pt * (256 * 4096) + mb * 64;
#pragma unroll
    for (int mt = 0; mt < 2; mt++) {
        int px0 = warp_m * 32 + mt * 16 + (lane >> 2);
#pragma unroll
        for (int nt = 0; nt < 8; nt++) {
            int oc = warp_n * 64 + nt * 8 + (lane & 3) * 2;
            float* p0 = Mp + (size_t)oc * 4096;
            p0[px0]            = acc[mt][nt][0] * ONE_M_EPS + accC[mt][nt][0];
            p0[4096 + px0]     = acc[mt][nt][1] * ONE_M_EPS + accC[mt][nt][1];
            p0[px0 + 8]        = acc[mt][nt][2] * ONE_M_EPS + accC[mt][nt][2];
            p0[4096 + px0 + 8] = acc[mt][nt][3] * ONE_M_EPS + accC[mt][nt][3];
        }
    }
}

// ---------------- output transform: Y = AT M A, demod, store ----------------
__global__ __launch_bounds__(256) void outT_kernel(float* __restrict__ out) {
    const int oc = blockIdx.x;
    const int n  = blockIdx.y;
    const int tid = threadIdx.x;
    const int th = tid >> 4, tw = tid & 15;
    const int flat = n * 256 + tid;

    float m6[6][6];
#pragma unroll
    for (int r = 0; r < 6; r++)
#pragma unroll
        for (int c = 0; c < 6; c++)
            m6[r][c] = g_M[(size_t)(r * 6 + c) * (256 * 4096) + (size_t)oc * 4096 + flat];

    float t2[4][6];
#pragma unroll
    for (int c = 0; c < 6; c++) {
        float m0 = m6[0][c], m1 = m6[1][c], m2 = m6[2][c], m3 = m6[3][c], m4 = m6[4][c], m5 = m6[5][c];
        t2[0][c] = m0 + m1 + m2 + m3 + m4;
        t2[1][c] = m1 - m2 + 2.f * m3 - 2.f * m4;
        t2[2][c] = m1 + m2 + 4.f * m3 + 4.f * m4;
        t2[3][c] = m1 - m2 + 8.f * m3 - 8.f * m4 + m5;
    }
    const float dm = g_demod[n * OC + oc];
    float* op = out + ((size_t)(n * OC + oc)) * 4096 + th * 4 * 64 + tw * 4;
#pragma unroll
    for (int i = 0; i < 4; i++) {
        float q0 = t2[i][0], q1 = t2[i][1], q2 = t2[i][2], q3 = t2[i][3], q4 = t2[i][4], q5 = t2[i][5];
        float4 y;
        y.x = (q0 + q1 + q2 + q3 + q4) * dm;
        y.y = (q1 - q2 + 2.f * q3 - 2.f * q4) * dm;
        y.z = (q1 + q2 + 4.f * q3 + 4.f * q4) * dm;
        y.w = (q1 - q2 + 8.f * q3 - 8.f * q4 + q5) * dm;
        *(float4*)(op + i * 64) = y;
    }
}

// ---------------------------------------------------------------------------
extern "C" void kernel_launch(void* const* d_in, const int* in_sizes, int n_in,
                              void* d_out, int out_size) {
    const float* x      = (const float*)d_in[0];
    const float* style  = (const float*)d_in[1];
    const float* weight = (const float*)d_in[2];
    const float* mod_w  = (const float*)d_in[3];
    const float* mod_b  = (const float*)d_in[4];
    float* out = (float*)d_out;

    cudaFuncSetAttribute(wino_gemm, cudaFuncAttributeMaxDynamicSharedMemorySize, SMEM_G);
    cudaFuncSetAttribute(inT_kernel, cudaFuncAttributeMaxDynamicSharedMemorySize, 2 * SM_INT);

    mod_kernel<<<N_B, 256>>>(style, mod_w, mod_b);
    wT_kernel<<<256, 256>>>(weight);     // also produces g_wsq
    demod_kernel<<<N_B, 256>>>();
    inT_kernel<<<dim3(16, 16, 16), 256, 2 * SM_INT>>>(x);
    wino_gemm<<<dim3(64, 36), 256, SMEM_G>>>();
    outT_kernel<<<dim3(256, 16), 256>>>(out);
}

// round 13
// speedup vs baseline: 1.0533x; 1.0533x over previous
#include <cuda_runtime.h>
#include <cuda_fp16.h>
#include <cstdint>

#define N_B 16
#define IC  256
#define OC  256
#define HH  64
#define WW  64
#define SD  512
#define EPSV 1e-8f

// Karatsuba fold scale: corrections = one MMA of (AL + EPS*AH)(BH + BL/EPS)
#define EPS_F   0.015625f      // 2^-6
#define EPS_INV 64.0f          // 2^6
#define ONE_M_EPS 0.984375f    // 1 - 2^-6 (exact in fp32)

// ---------------- device scratch ----------------
__device__ float g_m[N_B * IC];
__device__ float g_demod[N_B * OC];
__device__ float g_wsq[IC * OC];
// V: [pt(36)][mblock(32)][kc(4)][plane(2: hi, folded-corr)][128 rows x 64 ic swizzled] fp16
__device__ __align__(16) __half g_V[36 * 32 * 4 * 2 * 8192];
// U: [pt(36)][nh(2)][kc(4)][plane(2: hi, folded-corr)][128 oc x 64 ic swizzled] fp16
__device__ __align__(16) __half g_U[36 * 2 * 4 * 2 * 8192];
// M: [pt(36)][oc(256)][flat_tile(4096)] fp32
__device__ float g_M[36 * 256 * 4096];

// ---------------- PTX helpers ----------------
__device__ __forceinline__ uint32_t smem_u32(const void* p) {
    uint32_t a;
    asm("{ .reg .u64 t; cvta.to.shared.u64 t, %1; cvt.u32.u64 %0, t; }" : "=r"(a) : "l"(p));
    return a;
}
#define LDSM_X4(r0, r1, r2, r3, addr) \
    asm volatile("ldmatrix.sync.aligned.m8n8.x4.shared.b16 {%0,%1,%2,%3}, [%4];" \
        : "=r"(r0), "=r"(r1), "=r"(r2), "=r"(r3) : "r"(addr))
#define MMA16816(c, a, b0, b1) \
    asm volatile("mma.sync.aligned.m16n8k16.row.col.f32.f16.f16.f32 " \
        "{%0,%1,%2,%3}, {%4,%5,%6,%7}, {%8,%9}, {%0,%1,%2,%3};" \
        : "+f"((c)[0]), "+f"((c)[1]), "+f"((c)[2]), "+f"((c)[3]) \
        : "r"((a)[0]), "r"((a)[1]), "r"((a)[2]), "r"((a)[3]), "r"(b0), "r"(b1))
#define CP_ASYNC16(dst, src) \
    asm volatile("cp.async.cg.shared.global [%0], [%1], 16;" :: "r"(dst), "l"(src))
#define CP_COMMIT() asm volatile("cp.async.commit_group;")

// ---------------- weight transform: U = G g G^T, Karatsuba-fold split + swizzle
// also computes wsq (fused). Runs FIRST (mod_kernel consumes g_wsq). ----------------
__global__ void wT_kernel(const float* __restrict__ weight) {
    int idx = blockIdx.x * 256 + threadIdx.x;   // 0..65535
    int oc = idx >> 8, ic = idx & 255;
    float g[3][3];
    float sq = 0.f;
#pragma unroll
    for (int r = 0; r < 3; r++)
#pragma unroll
        for (int c = 0; c < 3; c++) {
            float w = weight[(oc * IC + ic) * 9 + r * 3 + c];
            g[r][c] = w;
            sq += w * w;
        }
    g_wsq[ic * OC + oc] = sq;

    float t[6][3];
#pragma unroll
    for (int c = 0; c < 3; c++) {
        float g0 = g[0][c], g1 = g[1][c], g2 = g[2][c];
        t[0][c] = 0.25f * g0;
        t[1][c] = (-g0 - g1 - g2) * (1.f / 6.f);
        t[2][c] = (-g0 + g1 - g2) * (1.f / 6.f);
        t[3][c] = g0 * (1.f / 24.f) + g1 * (1.f / 12.f) + g2 * (1.f / 6.f);
        t[4][c] = g0 * (1.f / 24.f) - g1 * (1.f / 12.f) + g2 * (1.f / 6.f);
        t[5][c] = g2;
    }
    const int nh = oc >> 7, oc128 = oc & 127;
    const int kc = ic >> 6, icc = ic & 63, kg = icc >> 3, kl = icc & 7;
    const int off16 = oc128 * 64 + ((kg ^ (oc128 & 7)) << 3) + kl;
#pragma unroll
    for (int r = 0; r < 6; r++) {
        float t0 = t[r][0], t1 = t[r][1], t2 = t[r][2];
        float u[6];
        u[0] = 0.25f * t0;
        u[1] = (-t0 - t1 - t2) * (1.f / 6.f);
        u[2] = (-t0 + t1 - t2) * (1.f / 6.f);
        u[3] = t0 * (1.f / 24.f) + t1 * (1.f / 12.f) + t2 * (1.f / 6.f);
        u[4] = t0 * (1.f / 24.f) - t1 * (1.f / 12.f) + t2 * (1.f / 6.f);
        u[5] = t2;
#pragma unroll
        for (int c = 0; c < 6; c++) {
            int pt = r * 6 + c;
            __half h = __float2half_rn(u[c]);
            float hf = __half2float(h);
            __half bcv = __float2half_rn(hf + EPS_INV * (u[c] - hf));   // Bc = BH + BL/eps
            size_t base = ((size_t)(((pt * 2 + nh) * 4 + kc) * 2)) * 8192;
            g_U[base + off16] = h;
            g_U[base + 8192 + off16] = bcv;
        }
    }
}

// ---------------- modulation + demod (fused; needs g_wsq from wT) ----------------
__global__ void mod_kernel(const float* __restrict__ style,
                           const float* __restrict__ mod_w,
                           const float* __restrict__ mod_b) {
    int n = blockIdx.x, i = threadIdx.x;
    __shared__ float ss[SD];
    __shared__ float ms[IC];
    for (int k = threadIdx.x; k < SD; k += blockDim.x) ss[k] = style[n * SD + k];
    __syncthreads();
    float acc = 0.f;
    const float* wr = mod_w + i * SD;
#pragma unroll 8
    for (int k = 0; k < SD; k++) acc += ss[k] * wr[k];
    float mi = acc + mod_b[i] + 1.0f;
    g_m[n * IC + i] = mi;
    ms[i] = mi;
    __syncthreads();
    float a2 = EPSV;
#pragma unroll 8
    for (int ic = 0; ic < IC; ic++) a2 += ms[ic] * ms[ic] * g_wsq[ic * OC + i];
    g_demod[n * OC + i] = rsqrtf(a2);
}

// ---------------- input transform: V = B^T (x*m) B, Karatsuba-fold split + swizzle
// All 36 points staged into smem, ONE barrier, one batched flush.
#define SM_INT (36 * 16 * 24 * 2)       // bytes per plane: 27648
__global__ __launch_bounds__(256) void inT_kernel(const float* __restrict__ x) {
    extern __shared__ __align__(16) unsigned char smem[];
    __half* sH = (__half*)smem;                    // [36][16][24]
    __half* sL = (__half*)(smem + SM_INT);

    const int icg = blockIdx.x;            // 16-ic group (0..15)
    const int th  = blockIdx.y;            // tile row (0..15)
    const int n   = blockIdx.z;
    const int tid = threadIdx.x;
    const int tw  = tid & 15, icl = tid >> 4;
    const int ic  = icg * 16 + icl;

    const float mm = g_m[n * IC + ic];
    const float* xp = x + ((size_t)(n * IC + ic)) * 4096;

    float d[6][6];
#pragma unroll
    for (int r = 0; r < 6; r++) {
        int gh = th * 4 + r - 1;
#pragma unroll
        for (int c = 0; c < 6; c++) {
            int gw = tw * 4 + c - 1;
            d[r][c] = ((unsigned)gh < HH && (unsigned)gw < WW) ? xp[gh * 64 + gw] * mm : 0.f;
        }
    }
    float t[6][6];
#pragma unroll
    for (int c = 0; c < 6; c++) {
        float d0 = d[0][c], d1 = d[1][c], d2 = d[2][c], d3 = d[3][c], d4 = d[4][c], d5 = d[5][c];
        t[0][c] = 4.f * d0 - 5.f * d2 + d4;
        t[1][c] = -4.f * d1 - 4.f * d2 + d3 + d4;
        t[2][c] = 4.f * d1 - 4.f * d2 - d3 + d4;
        t[3][c] = -2.f * d1 - d2 + 2.f * d3 + d4;
        t[4][c] = 2.f * d1 - d2 - 2.f * d3 + d4;
        t[5][c] = 4.f * d1 - 5.f * d3 + d5;
    }

#pragma unroll
    for (int r = 0; r < 6; r++) {
        float t0 = t[r][0], t1 = t[r][1], t2 = t[r][2], t3 = t[r][3], t4 = t[r][4], t5 = t[r][5];
        float v[6];
        v[0] = 4.f * t0 - 5.f * t2 + t4;
        v[1] = -4.f * t1 - 4.f * t2 + t3 + t4;
        v[2] = 4.f * t1 - 4.f * t2 - t3 + t4;
        v[3] = -2.f * t1 - t2 + 2.f * t3 + t4;
        v[4] = 2.f * t1 - t2 - 2.f * t3 + t4;
        v[5] = 4.f * t1 - 5.f * t3 + t5;
#pragma unroll
        for (int c = 0; c < 6; c++) {
            __half h = __float2half_rn(v[c]);
            float hf = __half2float(h);
            __half acv = __float2half_rn((v[c] - hf) + EPS_F * hf);   // Ac = AL + eps*AH
            int off = ((r * 6 + c) * 16 + tw) * 24 + icl;
            sH[off] = h;
            sL[off] = acv;
        }
    }
    __syncthreads();

    const int mb = n * 2 + (th >> 3);
    const int kc = icg >> 2;
    const int rowbase = (th & 7) * 16;

    // flush: 36 pts x 2 planes x 16 rows x 2 granules = 2304 uint4 -> 9/thread
#pragma unroll
    for (int k = 0; k < 9; k++) {
        int it = tid + k * 256;
        int pt = it / 64;
        int rest = it & 63;
        int plane = rest >> 5;
        int e = rest & 31;
        int rw = e >> 1, gsel = e & 1;
        int kg = (icg & 3) * 2 + gsel;
        const __half* srcp = plane ? sL : sH;
        const uint4* src = (const uint4*)(srcp + (pt * 16 + rw) * 24 + gsel * 8);
        size_t base = ((size_t)(((pt * 32 + mb) * 4 + kc) * 2 + plane)) * 8192;
        *(uint4*)(g_V + base + (rowbase + rw) * 64 + ((kg ^ (rw & 7)) << 3)) = *src;
    }
}

// ---------------- batched GEMM: M[pt] = V[pt] * U[pt]^T ----------------
// M-tile = 64 -> 2 CTAs/SM. hi*hi fp32-acc + one folded correction MMA per n8 per k16.
// Grid order (nh, mb, pt): the two nh CTAs sharing one V tile are launch-adjacent -> L2 reuse.
#define STAGE_B 49152                      // per stage: Ahi 8K | Acorr 8K | Bhi 16K | Bcorr 16K
#define SMEM_G  (2 * STAGE_B)
__global__ __launch_bounds__(256, 2)
void wino_gemm() {
    extern __shared__ __align__(128) unsigned char smem[];
    const uint32_t sb = smem_u32(smem);
    const int tid = threadIdx.x;
    const int wid = tid >> 5, lane = tid & 31;
    const int nh = blockIdx.x;             // 0..1  (fastest -> L2 reuse of V)
    const int mb = blockIdx.y;             // 0..63 (64-row block)
    const int pt = blockIdx.z;             // 0..35
    const int mb2 = mb >> 1, hb = mb & 1;

    const int warp_m = wid & 1, warp_n = wid >> 1;
    const int pxr0 = warp_m * 32 + (lane & 15);
    const int aksel = lane >> 4;
    const uint32_t bboff = (uint32_t)(warp_n * 32 + ((lane >> 4) << 3) + (lane & 7)) * 128;
    const int bksel = (lane >> 3) & 1;
    const int bswz = lane & 7;

    float acc[2][4][4];
    float accC[2][4][4];
#pragma unroll
    for (int a = 0; a < 2; a++)
#pragma unroll
        for (int b = 0; b < 4; b++)
#pragma unroll
            for (int q = 0; q < 4; q++) { acc[a][b][q] = 0.f; accC[a][b][q] = 0.f; }

    // prologue: chunk 0 -> stage 0
    {
#pragma unroll
        for (int p = 0; p < 2; p++) {
            const char* As = (const char*)(g_V + ((size_t)(((pt * 32 + mb2) * 4 + 0) * 2 + p)) * 8192 + (size_t)hb * 4096);
            const char* Bs = (const char*)(g_U + ((size_t)(((pt * 2 + nh) * 4 + 0) * 2 + p)) * 8192);
#pragma unroll
            for (int i = 0; i < 2; i++)
                CP_ASYNC16(sb + p * 8192 + (tid + i * 256) * 16, As + (tid + i * 256) * 16);
#pragma unroll
            for (int i = 0; i < 4; i++)
                CP_ASYNC16(sb + 16384 + p * 16384 + (tid + i * 256) * 16, Bs + (tid + i * 256) * 16);
        }
        CP_COMMIT();
    }

#pragma unroll 1
    for (int kc = 0; kc < 4; kc++) {
        const int s = kc & 1;
        __syncthreads();
        if (kc + 1 < 4) {
            uint32_t dA = sb + (s ^ 1) * STAGE_B;
#pragma unroll
            for (int p = 0; p < 2; p++) {
                const char* As = (const char*)(g_V + ((size_t)(((pt * 32 + mb2) * 4 + kc + 1) * 2 + p)) * 8192 + (size_t)hb * 4096);
                const char* Bs = (const char*)(g_U + ((size_t)(((pt * 2 + nh) * 4 + kc + 1) * 2 + p)) * 8192);
#pragma unroll
                for (int i = 0; i < 2; i++)
                    CP_ASYNC16(dA + p * 8192 + (tid + i * 256) * 16, As + (tid + i * 256) * 16);
#pragma unroll
                for (int i = 0; i < 4; i++)
                    CP_ASYNC16(dA + 16384 + p * 16384 + (tid + i * 256) * 16, Bs + (tid + i * 256) * 16);
            }
            CP_COMMIT();
            asm volatile("cp.async.wait_group 1;");
        } else {
            asm volatile("cp.async.wait_group 0;");
        }
        __syncthreads();

        const uint32_t Abase = sb + s * STAGE_B;
        const uint32_t Bbase = Abase + 16384 + bboff;
#pragma unroll
        for (int st = 0; st < 4; st++) {
            uint32_t AH[2][4], AC[2][4];
#pragma unroll
            for (int mt = 0; mt < 2; mt++) {
                int row = pxr0 + mt * 16;
                int kg = 2 * st + aksel;
                uint32_t a = Abase + (uint32_t)row * 128 + ((uint32_t)(kg ^ (row & 7)) << 4);
                LDSM_X4(AH[mt][0], AH[mt][1], AH[mt][2], AH[mt][3], a);
                LDSM_X4(AC[mt][0], AC[mt][1], AC[mt][2], AC[mt][3], a + 8192);
            }
            int kgb = 2 * st + bksel;
            uint32_t boff = (uint32_t)((kgb ^ bswz) << 4);
#pragma unroll
            for (int og = 0; og < 2; og++) {
                uint32_t BH[4], BC[4];
                uint32_t ba = Bbase + og * 2048 + boff;
                LDSM_X4(BH[0], BH[1], BH[2], BH[3], ba);
                LDSM_X4(BC[0], BC[1], BC[2], BC[3], ba + 16384);
#pragma unroll
                for (int mt = 0; mt < 2; mt++) {
                    MMA16816(acc[mt][og * 2],      AH[mt], BH[0], BH[1]);
                    MMA16816(acc[mt][og * 2 + 1],  AH[mt], BH[2], BH[3]);
                    MMA16816(accC[mt][og * 2],     AC[mt], BC[0], BC[1]);
                    MMA16816(accC[mt][og * 2 + 1], AC[mt], BC[2], BC[3]);
                }
            }
        }
    }

    // epilogue: final = acc_hi*(1-eps) + acc_corr ; store M
    float* Mp = g_M + (size_t)pt * (256 * 4096) + mb * 64;
#pragma unroll
    for (int mt = 0; mt < 2; mt++) {
        int px0 = warp_m * 32 + mt * 16 + (lane >> 2);
#pragma unroll
        for (int nt = 0; nt < 4; nt++) {
            int oc = nh * 128 + warp_n * 32 + nt * 8 + (lane & 3) * 2;
            float* p0 = Mp + (size_t)oc * 4096;
            p0[px0]            = acc[mt][nt][0] * ONE_M_EPS + accC[mt][nt][0];
            p0[4096 + px0]     = acc[mt][nt][1] * ONE_M_EPS + accC[mt][nt][1];
            p0[px0 + 8]        = acc[mt][nt][2] * ONE_M_EPS + accC[mt][nt][2];
            p0[4096 + px0 + 8] = acc[mt][nt][3] * ONE_M_EPS + accC[mt][nt][3];
        }
    }
}

// ---------------- output transform: Y = AT M A, demod, store ----------------
// Streams over r (6 loads live at a time) -> fewer live regs, batched MLP.
__global__ __launch_bounds__(256) void outT_kernel(float* __restrict__ out) {
    const int oc = blockIdx.x;
    const int n  = blockIdx.y;
    const int tid = threadIdx.x;
    const int th = tid >> 4, tw = tid & 15;
    const int flat = n * 256 + tid;

    const float* Mbase = g_M + (size_t)oc * 4096 + flat;

    float t2[4][6];
#pragma unroll
    for (int i = 0; i < 4; i++)
#pragma unroll
        for (int c = 0; c < 6; c++) t2[i][c] = 0.f;

#pragma unroll
    for (int r = 0; r < 6; r++) {
        float mr[6];
#pragma unroll
        for (int c = 0; c < 6; c++)
            mr[c] = Mbase[(size_t)(r * 6 + c) * (256 * 4096)];
        if (r == 0) {
#pragma unroll
            for (int c = 0; c < 6; c++) t2[0][c] += mr[c];
        } else if (r == 5) {
#pragma unroll
            for (int c = 0; c < 6; c++) t2[3][c] += mr[c];
        } else {
            const float s1 = (r == 2 || r == 4) ? -1.f : 1.f;
            const float w13 = (r <= 2) ? 1.f : 2.f;   // |coef| for row i=1: r1,r2 ->1; r3,r4 ->2
            const float w2  = (r <= 2) ? 1.f : 4.f;
            const float w3  = (r <= 2) ? 1.f : 8.f;
#pragma unroll
            for (int c = 0; c < 6; c++) {
                float v = mr[c];
                t2[0][c] += v;
                t2[1][c] += s1 * w13 * v;
                t2[2][c] += w2 * v;
                t2[3][c] += s1 * w3 * v;
            }
        }
    }

    const float dm = g_demod[n * OC + oc];
    float* op = out + ((size_t)(n * OC + oc)) * 4096 + th * 4 * 64 + tw * 4;
#pragma unroll
    for (int i = 0; i < 4; i++) {
        float q0 = t2[i][0], q1 = t2[i][1], q2 = t2[i][2], q3 = t2[i][3], q4 = t2[i][4], q5 = t2[i][5];
        float4 y;
        y.x = (q0 + q1 + q2 + q3 + q4) * dm;
        y.y = (q1 - q2 + 2.f * q3 - 2.f * q4) * dm;
        y.z = (q1 + q2 + 4.f * q3 + 4.f * q4) * dm;
        y.w = (q1 - q2 + 8.f * q3 - 8.f * q4 + q5) * dm;
        *(float4*)(op + i * 64) = y;
    }
}

// ---------------------------------------------------------------------------
extern "C" void kernel_launch(void* const* d_in, const int* in_sizes, int n_in,
                              void* d_out, int out_size) {
    const float* x      = (const float*)d_in[0];
    const float* style  = (const float*)d_in[1];
    const float* weight = (const float*)d_in[2];
    const float* mod_w  = (const float*)d_in[3];
    const float* mod_b  = (const float*)d_in[4];
    float* out = (float*)d_out;

    cudaFuncSetAttribute(wino_gemm, cudaFuncAttributeMaxDynamicSharedMemorySize, SMEM_G);
    cudaFuncSetAttribute(inT_kernel, cudaFuncAttributeMaxDynamicSharedMemorySize, 2 * SM_INT);

    wT_kernel<<<256, 256>>>(weight);                    // produces g_U + g_wsq
    mod_kernel<<<N_B, 256>>>(style, mod_w, mod_b);      // produces g_m + g_demod (fused)
    inT_kernel<<<dim3(16, 16, 16), 256, 2 * SM_INT>>>(x);
    wino_gemm<<<dim3(2, 64, 36), 256, SMEM_G>>>();
    outT_kernel<<<dim3(256, 16), 256>>>(out);
}